// round 13
// baseline (speedup 1.0000x reference)
#include <cuda_runtime.h>
#include <cuda_bf16.h>

// DiffJPEG per-8x8-block: D @ X @ D^T -> round(./Q)*Q -> D^T @ M @ D
// R13 = R12 (two threads per block, shfl.xor(1) pair exchange, f32x2
// butterfly + magic rounding) with:
//   1. __launch_bounds__(256,4): regs=64 -> 4 CTAs/SM, 32 warps (50% occ).
//   2. Quant constants from a global float4 LUT (L1-hot) instead of 64
//      per-lane SELs -> ~48 fewer issue slots/thread, alu pipe off-loaded.

using u64 = unsigned long long;

// D[i][j] = c_i * cos((2j+1) i pi / 16), c_0 = sqrt(1/8), else 0.5
__device__ constexpr float DMc[8][8] = {
    { 0.3535533905932738f,  0.3535533905932738f,  0.3535533905932738f,  0.3535533905932738f,
      0.3535533905932738f,  0.3535533905932738f,  0.3535533905932738f,  0.3535533905932738f },
    { 0.4903926402016152f,  0.4157348061512726f,  0.2777851165098011f,  0.0975451610080642f,
     -0.0975451610080642f, -0.2777851165098011f, -0.4157348061512726f, -0.4903926402016152f },
    { 0.4619397662556434f,  0.1913417161825449f, -0.1913417161825449f, -0.4619397662556434f,
     -0.4619397662556434f, -0.1913417161825449f,  0.1913417161825449f,  0.4619397662556434f },
    { 0.4157348061512726f, -0.0975451610080642f, -0.4903926402016152f, -0.2777851165098011f,
      0.2777851165098011f,  0.4903926402016152f,  0.0975451610080642f, -0.4157348061512726f },
    { 0.3535533905932738f, -0.3535533905932738f, -0.3535533905932738f,  0.3535533905932738f,
      0.3535533905932738f, -0.3535533905932738f, -0.3535533905932738f,  0.3535533905932738f },
    { 0.2777851165098011f, -0.4903926402016152f,  0.0975451610080642f,  0.4157348061512726f,
     -0.4157348061512726f, -0.0975451610080642f,  0.4903926402016152f, -0.2777851165098011f },
    { 0.1913417161825449f, -0.4619397662556434f,  0.4619397662556434f, -0.1913417161825449f,
     -0.1913417161825449f,  0.4619397662556434f, -0.4619397662556434f,  0.1913417161825449f },
    { 0.0975451610080642f, -0.2777851165098011f,  0.4157348061512726f, -0.4903926402016152f,
      0.4903926402016152f, -0.4157348061512726f,  0.2777851165098011f, -0.0975451610080642f },
};

// quality=50 -> Q == q_luma exactly.
__device__ constexpr float QMc[8][8] = {
    { 16.f, 11.f, 10.f, 16.f,  24.f,  40.f,  51.f,  61.f },
    { 12.f, 12.f, 14.f, 19.f,  26.f,  58.f,  60.f,  55.f },
    { 14.f, 13.f, 16.f, 24.f,  40.f,  57.f,  69.f,  56.f },
    { 14.f, 17.f, 22.f, 29.f,  51.f,  87.f,  80.f,  62.f },
    { 18.f, 22.f, 37.f, 56.f,  68.f, 109.f, 103.f,  77.f },
    { 24.f, 35.f, 55.f, 64.f,  81.f, 104.f, 113.f,  92.f },
    { 49.f, 64.f, 78.f, 87.f, 103.f, 121.f, 120.f, 101.f },
    { 72.f, 92.f, 95.f, 98.f, 112.f, 100.f, 103.f,  99.f },
};

// Quant LUT: QTab[row][t] = (1/Q[row][2t], 1/Q[row][2t+1], Q[row][2t], Q[row][2t+1])
#define QT4(g, t) { 1.0f/QMc[g][2*(t)], 1.0f/QMc[g][2*(t)+1], QMc[g][2*(t)], QMc[g][2*(t)+1] }
#define QROW(g)   { QT4(g,0), QT4(g,1), QT4(g,2), QT4(g,3) }
__device__ const float4 QTab[8][4] = {
    QROW(0), QROW(1), QROW(2), QROW(3), QROW(4), QROW(5), QROW(6), QROW(7)
};

__device__ __forceinline__ u64 pk(float a, float b) {
    u64 r; asm("mov.b64 %0, {%1, %2};" : "=l"(r) : "f"(a), "f"(b)); return r;
}
__device__ __forceinline__ void unpk(float& a, float& b, u64 v) {
    asm("mov.b64 {%0, %1}, %2;" : "=f"(a), "=f"(b) : "l"(v));
}
__device__ __forceinline__ u64 fma2(u64 a, u64 b, u64 c) {
    u64 d; asm("fma.rn.f32x2 %0, %1, %2, %3;" : "=l"(d) : "l"(a), "l"(b), "l"(c)); return d;
}
__device__ __forceinline__ u64 mul2(u64 a, u64 b) {
    u64 d; asm("mul.rn.f32x2 %0, %1, %2;" : "=l"(d) : "l"(a), "l"(b)); return d;
}
__device__ __forceinline__ u64 add2(u64 a, u64 b) {
    u64 d; asm("add.rn.f32x2 %0, %1, %2;" : "=l"(d) : "l"(a), "l"(b)); return d;
}
__device__ __forceinline__ u64 sub2(u64 a, u64 b, u64 neg1) {
    return fma2(b, neg1, a);   // a - b
}
// exchange a u64 with lane^1
__device__ __forceinline__ u64 shx1(u64 v) {
    unsigned lo, hi;
    asm("mov.b64 {%0, %1}, %2;" : "=r"(lo), "=r"(hi) : "l"(v));
    lo = __shfl_xor_sync(0xffffffffu, lo, 1);
    hi = __shfl_xor_sync(0xffffffffu, hi, 1);
    u64 r; asm("mov.b64 %0, {%1, %2};" : "=l"(r) : "r"(lo), "r"(hi));
    return r;
}

__global__ void __launch_bounds__(256, 4)
diffjpeg_kernel(const float* __restrict__ in, float* __restrict__ out, int nblk)
{
    const int gt  = blockIdx.x * 256 + threadIdx.x;   // global thread
    const int blk = gt >> 1;                          // 8x8 block index
    const bool h  = (gt & 1) != 0;                    // half: false=cols 0-3, true=cols 4-7
    if (blk >= nblk) return;

    const u64 NEG1   = pk(-1.0f, -1.0f);
    const u64 MAGIC2 = pk(12582912.0f, 12582912.0f);  // 1.5 * 2^23

    int bw  = blk & 63;
    int t1  = blk >> 6;
    int bh  = t1 & 63;
    int img = t1 >> 6;
    size_t base = ((size_t)img << 18) + ((size_t)bh << 12) + ((size_t)bw << 3)
                + (h ? 4u : 0u);                       // column offset of my half
    const float* p = in  + base;
    float*       q = out + base;

    // my quant rows: 4h .. 4h+3
    const float4* qbase = &QTab[h ? 4 : 0][0];

    // A[r][pp]: my 4 columns (2 packed pairs) of row r, r = 0..7
    u64 A[8][2];

    // ---- pass 1: column DCT via row butterfly (local to my 4 columns) -----
    #pragma unroll
    for (int t = 0; t < 4; ++t) {
        ulonglong2 xt = __ldcs(reinterpret_cast<const ulonglong2*>(p + (size_t)t * 512));
        ulonglong2 xb = __ldcs(reinterpret_cast<const ulonglong2*>(p + (size_t)(7 - t) * 512));
        u64 S[2]  = { add2(xt.x, xb.x),       add2(xt.y, xb.y) };
        u64 Dd[2] = { sub2(xt.x, xb.x, NEG1), sub2(xt.y, xb.y, NEG1) };
        #pragma unroll
        for (int u = 0; u < 4; ++u) {
            u64 ce = pk(DMc[2*u][t],   DMc[2*u][t]);
            u64 co = pk(DMc[2*u+1][t], DMc[2*u+1][t]);
            #pragma unroll
            for (int pp = 0; pp < 2; ++pp) {
                if (t == 0) {
                    A[2*u][pp]   = mul2(ce, S[pp]);
                    A[2*u+1][pp] = mul2(co, Dd[pp]);
                } else {
                    A[2*u][pp]   = fma2(ce, S[pp],  A[2*u][pp]);
                    A[2*u+1][pp] = fma2(co, Dd[pp], A[2*u+1][pp]);
                }
            }
        }
    }

    // ---- exchange 1: col-split -> row-split -------------------------------
    // After this, R[lr][cp] = global colpair cp (0..3) of global row 4h+lr.
    u64 R[4][4];
    #pragma unroll
    for (int lr = 0; lr < 4; ++lr) {
        #pragma unroll
        for (int pp = 0; pp < 2; ++pp) {
            u64 own  = h ? A[lr + 4][pp] : A[lr][pp];      // my cols, my row
            u64 send = h ? A[lr][pp]     : A[lr + 4][pp];  // my cols, partner's row
            u64 recv = shx1(send);
            R[lr][pp]     = h ? recv : own;                // colpairs 0..1
            R[lr][2 + pp] = h ? own  : recv;               // colpairs 2..3
        }
    }

    // ---- row phase: 4 full rows (global row gi = 4h+lr) -------------------
    #pragma unroll
    for (int lr = 0; lr < 4; ++lr) {
        float a0,a1,a2,a3,a4,a5,a6,a7;
        unpk(a0, a1, R[lr][0]); unpk(a2, a3, R[lr][1]);
        unpk(a4, a5, R[lr][2]); unpk(a6, a7, R[lr][3]);

        u64 sd[4];
        sd[0] = pk(a0 + a7, a0 - a7);
        sd[1] = pk(a1 + a6, a1 - a6);
        sd[2] = pk(a2 + a5, a2 - a5);
        sd[3] = pk(a3 + a4, a3 - a4);

        // row-fwd: independent of row index (DCT coeffs only)
        u64 r[4];
        #pragma unroll
        for (int t = 0; t < 4; ++t) {
            u64 acc = mul2(sd[0], pk(DMc[2*t][0], DMc[2*t+1][0]));
            #pragma unroll
            for (int j = 1; j < 4; ++j)
                acc = fma2(sd[j], pk(DMc[2*t][j], DMc[2*t+1][j]), acc);
            r[t] = acc;
        }

        // quant/dequant: packed constants from the L1-hot LUT (row 4h+lr)
        const float4* qrow = qbase + lr * 4;
        float m[8];
        #pragma unroll
        for (int t = 0; t < 4; ++t) {
            float4 f = __ldg(&qrow[t]);
            u64 qinv = pk(f.x, f.y);
            u64 qfwd = pk(f.z, f.w);
            u64 sc = mul2(r[t], qinv);
            u64 rr = add2(sc, MAGIC2);
            rr = sub2(rr, MAGIC2, NEG1);
            u64 mq = mul2(rr, qfwd);
            unpk(m[2*t], m[2*t+1], mq);
        }

        // row-inv butterfly (row-index independent)
        u64 U01, U23, V01, V23;
        {
            u64 be = pk(m[0], m[0]);
            U01 = mul2(be, pk(DMc[0][0], DMc[0][1]));
            U23 = mul2(be, pk(DMc[0][2], DMc[0][3]));
            u64 bo = pk(m[1], m[1]);
            V01 = mul2(bo, pk(DMc[1][0], DMc[1][1]));
            V23 = mul2(bo, pk(DMc[1][2], DMc[1][3]));
        }
        #pragma unroll
        for (int t = 1; t < 4; ++t) {
            u64 be = pk(m[2*t], m[2*t]);
            U01 = fma2(be, pk(DMc[2*t][0], DMc[2*t][1]), U01);
            U23 = fma2(be, pk(DMc[2*t][2], DMc[2*t][3]), U23);
            u64 bo = pk(m[2*t+1], m[2*t+1]);
            V01 = fma2(bo, pk(DMc[2*t+1][0], DMc[2*t+1][1]), V01);
            V23 = fma2(bo, pk(DMc[2*t+1][2], DMc[2*t+1][3]), V23);
        }
        R[lr][0] = add2(U01, V01);            // (P0, P1)
        R[lr][1] = add2(U23, V23);            // (P2, P3)
        u64 t76 = sub2(U01, V01, NEG1);       // (P7, P6)
        u64 t54 = sub2(U23, V23, NEG1);       // (P5, P4)
        { float x, y; unpk(x, y, t54); R[lr][2] = pk(y, x); }  // (P4, P5)
        { float x, y; unpk(x, y, t76); R[lr][3] = pk(y, x); }  // (P6, P7)
    }

    // ---- exchange 2: row-split -> col-split -------------------------------
    // B[r][pp] = my colpair (2h+pp) of global row r, r = 0..7
    u64 B[8][2];
    #pragma unroll
    for (int lr = 0; lr < 4; ++lr) {
        #pragma unroll
        for (int pp = 0; pp < 2; ++pp) {
            u64 own  = h ? R[lr][2 + pp] : R[lr][pp];      // my colpairs, my row
            u64 send = h ? R[lr][pp]     : R[lr][2 + pp];  // partner's colpairs, my row
            u64 recv = shx1(send);
            B[lr][pp]     = h ? recv : own;                // rows 0..3
            B[lr + 4][pp] = h ? own  : recv;               // rows 4..7
        }
    }

    // ---- pass 5: inverse column DCT via butterfly (local), streamed stores -
    #pragma unroll
    for (int i = 0; i < 4; ++i) {
        u64 u[2], v[2];
        {
            u64 ce = pk(DMc[0][i], DMc[0][i]);
            u64 co = pk(DMc[1][i], DMc[1][i]);
            #pragma unroll
            for (int pp = 0; pp < 2; ++pp) {
                u[pp] = mul2(ce, B[0][pp]);
                v[pp] = mul2(co, B[1][pp]);
            }
        }
        #pragma unroll
        for (int t = 1; t < 4; ++t) {
            u64 ce = pk(DMc[2*t][i], DMc[2*t][i]);
            u64 co = pk(DMc[2*t+1][i], DMc[2*t+1][i]);
            #pragma unroll
            for (int pp = 0; pp < 2; ++pp) {
                u[pp] = fma2(ce, B[2*t][pp], u[pp]);
                v[pp] = fma2(co, B[2*t+1][pp], v[pp]);
            }
        }
        __stcs(reinterpret_cast<ulonglong2*>(q + (size_t)i * 512),
               make_ulonglong2(add2(u[0], v[0]), add2(u[1], v[1])));
        __stcs(reinterpret_cast<ulonglong2*>(q + (size_t)(7 - i) * 512),
               make_ulonglong2(sub2(u[0], v[0], NEG1), sub2(u[1], v[1], NEG1)));
    }
}

extern "C" void kernel_launch(void* const* d_in, const int* in_sizes, int n_in,
                              void* d_out, int out_size)
{
    const float* in  = (const float*)d_in[0];
    float*       out = (float*)d_out;
    int nblk = in_sizes[0] / 64;                  // number of 8x8 blocks
    int nthr = nblk * 2;                          // two threads per block
    int grid = (nthr + 255) / 256;
    diffjpeg_kernel<<<grid, 256>>>(in, out, nblk);
}

// round 14
// speedup vs baseline: 1.0204x; 1.0204x over previous
#include <cuda_runtime.h>
#include <cuda_bf16.h>

// DiffJPEG per-8x8-block: D @ X @ D^T -> round(./Q)*Q -> D^T @ M @ D
// R14: warp-uniform pair split. Warp 2k (h=0, cols 0-3) pairs with warp 2k+1
// (h=1, cols 4-7), lane-for-lane. h is warp-uniform, so the lane-SELs of R12
// (exchange own/send/place + per-lane quant constants, ~190 issue slots) are
// replaced by smem exchanges (conflict-free STS/LDS.128) and uniform-branch
// code specialization with compile-time Q rows. f32x2 butterfly + magic
// rounding unchanged (bit-identical math, rel_err 0.0 since R3).

using u64 = unsigned long long;

// D[i][j] = c_i * cos((2j+1) i pi / 16), c_0 = sqrt(1/8), else 0.5
__device__ constexpr float DMc[8][8] = {
    { 0.3535533905932738f,  0.3535533905932738f,  0.3535533905932738f,  0.3535533905932738f,
      0.3535533905932738f,  0.3535533905932738f,  0.3535533905932738f,  0.3535533905932738f },
    { 0.4903926402016152f,  0.4157348061512726f,  0.2777851165098011f,  0.0975451610080642f,
     -0.0975451610080642f, -0.2777851165098011f, -0.4157348061512726f, -0.4903926402016152f },
    { 0.4619397662556434f,  0.1913417161825449f, -0.1913417161825449f, -0.4619397662556434f,
     -0.4619397662556434f, -0.1913417161825449f,  0.1913417161825449f,  0.4619397662556434f },
    { 0.4157348061512726f, -0.0975451610080642f, -0.4903926402016152f, -0.2777851165098011f,
      0.2777851165098011f,  0.4903926402016152f,  0.0975451610080642f, -0.4157348061512726f },
    { 0.3535533905932738f, -0.3535533905932738f, -0.3535533905932738f,  0.3535533905932738f,
      0.3535533905932738f, -0.3535533905932738f, -0.3535533905932738f,  0.3535533905932738f },
    { 0.2777851165098011f, -0.4903926402016152f,  0.0975451610080642f,  0.4157348061512726f,
     -0.4157348061512726f, -0.0975451610080642f,  0.4903926402016152f, -0.2777851165098011f },
    { 0.1913417161825449f, -0.4619397662556434f,  0.4619397662556434f, -0.1913417161825449f,
     -0.1913417161825449f,  0.4619397662556434f, -0.4619397662556434f,  0.1913417161825449f },
    { 0.0975451610080642f, -0.2777851165098011f,  0.4157348061512726f, -0.4903926402016152f,
      0.4903926402016152f, -0.4157348061512726f,  0.2777851165098011f, -0.0975451610080642f },
};

// quality=50 -> Q == q_luma exactly.
__device__ constexpr float QMc[8][8] = {
    { 16.f, 11.f, 10.f, 16.f,  24.f,  40.f,  51.f,  61.f },
    { 12.f, 12.f, 14.f, 19.f,  26.f,  58.f,  60.f,  55.f },
    { 14.f, 13.f, 16.f, 24.f,  40.f,  57.f,  69.f,  56.f },
    { 14.f, 17.f, 22.f, 29.f,  51.f,  87.f,  80.f,  62.f },
    { 18.f, 22.f, 37.f, 56.f,  68.f, 109.f, 103.f,  77.f },
    { 24.f, 35.f, 55.f, 64.f,  81.f, 104.f, 113.f,  92.f },
    { 49.f, 64.f, 78.f, 87.f, 103.f, 121.f, 120.f, 101.f },
    { 72.f, 92.f, 95.f, 98.f, 112.f, 100.f, 103.f,  99.f },
};

__device__ __forceinline__ u64 pk(float a, float b) {
    u64 r; asm("mov.b64 %0, {%1, %2};" : "=l"(r) : "f"(a), "f"(b)); return r;
}
__device__ __forceinline__ void unpk(float& a, float& b, u64 v) {
    asm("mov.b64 {%0, %1}, %2;" : "=f"(a), "=f"(b) : "l"(v));
}
__device__ __forceinline__ u64 fma2(u64 a, u64 b, u64 c) {
    u64 d; asm("fma.rn.f32x2 %0, %1, %2, %3;" : "=l"(d) : "l"(a), "l"(b), "l"(c)); return d;
}
__device__ __forceinline__ u64 mul2(u64 a, u64 b) {
    u64 d; asm("mul.rn.f32x2 %0, %1, %2;" : "=l"(d) : "l"(a), "l"(b)); return d;
}
__device__ __forceinline__ u64 add2(u64 a, u64 b) {
    u64 d; asm("add.rn.f32x2 %0, %1, %2;" : "=l"(d) : "l"(a), "l"(b)); return d;
}
__device__ __forceinline__ u64 sub2(u64 a, u64 b, u64 neg1) {
    return fma2(b, neg1, a);   // a - b
}

// Full row transform of global row GI (compile time): inputs c0..c3 = packed
// colpairs, outputs P[4] = (P0,P1)(P2,P3)(P4,P5)(P6,P7). Quant constants are
// immediates (GI known at compile time) -> zero selects.
template<int GI>
__device__ __forceinline__ void row_proc(u64 c0, u64 c1, u64 c2, u64 c3,
                                         u64 NEG1, u64 MAGIC2, u64 (&P)[4])
{
    float a0,a1,a2,a3,a4,a5,a6,a7;
    unpk(a0, a1, c0); unpk(a2, a3, c1);
    unpk(a4, a5, c2); unpk(a6, a7, c3);

    u64 sd[4];
    sd[0] = pk(a0 + a7, a0 - a7);
    sd[1] = pk(a1 + a6, a1 - a6);
    sd[2] = pk(a2 + a5, a2 - a5);
    sd[3] = pk(a3 + a4, a3 - a4);

    // row-fwd butterfly
    u64 r[4];
    #pragma unroll
    for (int t = 0; t < 4; ++t) {
        u64 acc = mul2(sd[0], pk(DMc[2*t][0], DMc[2*t+1][0]));
        #pragma unroll
        for (int j = 1; j < 4; ++j)
            acc = fma2(sd[j], pk(DMc[2*t][j], DMc[2*t+1][j]), acc);
        r[t] = acc;
    }

    // packed quant/dequant (magic RNE rounding), constants are immediates
    float m[8];
    #pragma unroll
    for (int t = 0; t < 4; ++t) {
        u64 sc = mul2(r[t], pk(1.0f / QMc[GI][2*t], 1.0f / QMc[GI][2*t+1]));
        u64 rr = add2(sc, MAGIC2);
        rr = sub2(rr, MAGIC2, NEG1);
        u64 mq = mul2(rr, pk(QMc[GI][2*t], QMc[GI][2*t+1]));
        unpk(m[2*t], m[2*t+1], mq);
    }

    // row-inv butterfly
    u64 U01, U23, V01, V23;
    {
        u64 be = pk(m[0], m[0]);
        U01 = mul2(be, pk(DMc[0][0], DMc[0][1]));
        U23 = mul2(be, pk(DMc[0][2], DMc[0][3]));
        u64 bo = pk(m[1], m[1]);
        V01 = mul2(bo, pk(DMc[1][0], DMc[1][1]));
        V23 = mul2(bo, pk(DMc[1][2], DMc[1][3]));
    }
    #pragma unroll
    for (int t = 1; t < 4; ++t) {
        u64 be = pk(m[2*t], m[2*t]);
        U01 = fma2(be, pk(DMc[2*t][0], DMc[2*t][1]), U01);
        U23 = fma2(be, pk(DMc[2*t][2], DMc[2*t][3]), U23);
        u64 bo = pk(m[2*t+1], m[2*t+1]);
        V01 = fma2(bo, pk(DMc[2*t+1][0], DMc[2*t+1][1]), V01);
        V23 = fma2(bo, pk(DMc[2*t+1][2], DMc[2*t+1][3]), V23);
    }
    P[0] = add2(U01, V01);            // (P0, P1)
    P[1] = add2(U23, V23);            // (P2, P3)
    u64 t76 = sub2(U01, V01, NEG1);   // (P7, P6)
    u64 t54 = sub2(U23, V23, NEG1);   // (P5, P4)
    { float x, y; unpk(x, y, t54); P[2] = pk(y, x); }  // (P4, P5)
    { float x, y; unpk(x, y, t76); P[3] = pk(y, x); }  // (P6, P7)
}

__global__ void __launch_bounds__(256, 4)
diffjpeg_kernel(const float* __restrict__ in, float* __restrict__ out, int nblk)
{
    // exchange stage: [k][writer_h][pairid] of 16B; lane stride 16B -> no conflicts
    __shared__ ulonglong2 xbuf[4][2][128];

    const int tid  = threadIdx.x;
    const int w    = tid >> 5;
    const int lane = tid & 31;
    const int h    = w & 1;                    // warp-uniform half
    const int pid  = ((w >> 1) << 5) | lane;   // pair id 0..127

    int blk = blockIdx.x * 128 + pid;
    if (blk >= nblk) blk = nblk - 1;           // tail CTAs duplicate last blocks
                                               // (identical racing writes, benign)
    const u64 NEG1   = pk(-1.0f, -1.0f);
    const u64 MAGIC2 = pk(12582912.0f, 12582912.0f);  // 1.5 * 2^23

    int bw  = blk & 63;
    int t1  = blk >> 6;
    int bh  = t1 & 63;
    int img = t1 >> 6;
    size_t base = ((size_t)img << 18) + ((size_t)bh << 12) + ((size_t)bw << 3)
                + (size_t)(h << 2);            // my 4-column half
    const float* p = in  + base;
    float*       q = out + base;

    // A[r][pp]: my 4 columns (2 packed pairs) of global row r
    u64 A[8][2];

    // ---- pass 1: column DCT via row butterfly (local to my 4 columns) -----
    #pragma unroll
    for (int t = 0; t < 4; ++t) {
        ulonglong2 xt = __ldcs(reinterpret_cast<const ulonglong2*>(p + (size_t)t * 512));
        ulonglong2 xb = __ldcs(reinterpret_cast<const ulonglong2*>(p + (size_t)(7 - t) * 512));
        u64 S[2]  = { add2(xt.x, xb.x),       add2(xt.y, xb.y) };
        u64 Dd[2] = { sub2(xt.x, xb.x, NEG1), sub2(xt.y, xb.y, NEG1) };
        #pragma unroll
        for (int u = 0; u < 4; ++u) {
            u64 ce = pk(DMc[2*u][t],   DMc[2*u][t]);
            u64 co = pk(DMc[2*u+1][t], DMc[2*u+1][t]);
            #pragma unroll
            for (int pp = 0; pp < 2; ++pp) {
                if (t == 0) {
                    A[2*u][pp]   = mul2(ce, S[pp]);
                    A[2*u+1][pp] = mul2(co, Dd[pp]);
                } else {
                    A[2*u][pp]   = fma2(ce, S[pp],  A[2*u][pp]);
                    A[2*u+1][pp] = fma2(co, Dd[pp], A[2*u+1][pp]);
                }
            }
        }
    }

    // ---- exchange 1 (smem): send the 4 rows the partner needs -------------
    if (h == 0) {
        #pragma unroll
        for (int k = 0; k < 4; ++k)
            xbuf[k][0][pid] = make_ulonglong2(A[4 + k][0], A[4 + k][1]); // rows 4-7
    } else {
        #pragma unroll
        for (int k = 0; k < 4; ++k)
            xbuf[k][1][pid] = make_ulonglong2(A[k][0], A[k][1]);         // rows 0-3
    }
    __syncthreads();
    ulonglong2 recv[4];
    #pragma unroll
    for (int k = 0; k < 4; ++k)
        recv[k] = xbuf[k][h ^ 1][pid];
    __syncthreads();                           // all reads done before reuse

    // ---- row phase (warp-specialized, compile-time Q rows) + exchange-2 wr -
    u64 B[8][2];                               // col-split result
    if (h == 0) {
        #pragma unroll
        for (int lr = 0; lr < 4; ++lr) {
            u64 P[4];
            switch (lr) {  // compile-time GI = lr (rows 0-3)
            case 0: row_proc<0>(A[0][0], A[0][1], recv[0].x, recv[0].y, NEG1, MAGIC2, P); break;
            case 1: row_proc<1>(A[1][0], A[1][1], recv[1].x, recv[1].y, NEG1, MAGIC2, P); break;
            case 2: row_proc<2>(A[2][0], A[2][1], recv[2].x, recv[2].y, NEG1, MAGIC2, P); break;
            default: row_proc<3>(A[3][0], A[3][1], recv[3].x, recv[3].y, NEG1, MAGIC2, P); break;
            }
            B[lr][0] = P[0]; B[lr][1] = P[1];                  // keep cols 0-3
            xbuf[lr][0][pid] = make_ulonglong2(P[2], P[3]);    // send cols 4-7
        }
    } else {
        #pragma unroll
        for (int lr = 0; lr < 4; ++lr) {
            u64 P[4];
            switch (lr) {  // compile-time GI = 4+lr (rows 4-7)
            case 0: row_proc<4>(recv[0].x, recv[0].y, A[4][0], A[4][1], NEG1, MAGIC2, P); break;
            case 1: row_proc<5>(recv[1].x, recv[1].y, A[5][0], A[5][1], NEG1, MAGIC2, P); break;
            case 2: row_proc<6>(recv[2].x, recv[2].y, A[6][0], A[6][1], NEG1, MAGIC2, P); break;
            default: row_proc<7>(recv[3].x, recv[3].y, A[7][0], A[7][1], NEG1, MAGIC2, P); break;
            }
            B[4 + lr][0] = P[2]; B[4 + lr][1] = P[3];          // keep cols 4-7
            xbuf[lr][1][pid] = make_ulonglong2(P[0], P[1]);    // send cols 0-3
        }
    }
    __syncthreads();

    // ---- exchange 2 read: complete my col-split matrix --------------------
    if (h == 0) {
        #pragma unroll
        for (int k = 0; k < 4; ++k) {
            ulonglong2 t = xbuf[k][1][pid];    // cols 0-3 of rows 4-7
            B[4 + k][0] = t.x; B[4 + k][1] = t.y;
        }
    } else {
        #pragma unroll
        for (int k = 0; k < 4; ++k) {
            ulonglong2 t = xbuf[k][0][pid];    // cols 4-7 of rows 0-3
            B[k][0] = t.x; B[k][1] = t.y;
        }
    }

    // ---- pass 5: inverse column DCT via butterfly (local), streamed stores -
    #pragma unroll
    for (int i = 0; i < 4; ++i) {
        u64 u[2], v[2];
        {
            u64 ce = pk(DMc[0][i], DMc[0][i]);
            u64 co = pk(DMc[1][i], DMc[1][i]);
            #pragma unroll
            for (int pp = 0; pp < 2; ++pp) {
                u[pp] = mul2(ce, B[0][pp]);
                v[pp] = mul2(co, B[1][pp]);
            }
        }
        #pragma unroll
        for (int t = 1; t < 4; ++t) {
            u64 ce = pk(DMc[2*t][i], DMc[2*t][i]);
            u64 co = pk(DMc[2*t+1][i], DMc[2*t+1][i]);
            #pragma unroll
            for (int pp = 0; pp < 2; ++pp) {
                u[pp] = fma2(ce, B[2*t][pp], u[pp]);
                v[pp] = fma2(co, B[2*t+1][pp], v[pp]);
            }
        }
        __stcs(reinterpret_cast<ulonglong2*>(q + (size_t)i * 512),
               make_ulonglong2(add2(u[0], v[0]), add2(u[1], v[1])));
        __stcs(reinterpret_cast<ulonglong2*>(q + (size_t)(7 - i) * 512),
               make_ulonglong2(sub2(u[0], v[0], NEG1), sub2(u[1], v[1], NEG1)));
    }
}

extern "C" void kernel_launch(void* const* d_in, const int* in_sizes, int n_in,
                              void* d_out, int out_size)
{
    const float* in  = (const float*)d_in[0];
    float*       out = (float*)d_out;
    int nblk = in_sizes[0] / 64;                  // number of 8x8 blocks
    int grid = (nblk + 127) / 128;                // 128 block-pairs per CTA
    diffjpeg_kernel<<<grid, 256>>>(in, out, nblk);
}